// round 12
// baseline (speedup 1.0000x reference)
#include <cuda_runtime.h>
#include <math.h>

// ---------------- problem constants ----------------
#define BATCH 4
#define SEQ   2048
#define DM    1024
#define DV    64
#define MTOT  (BATCH * SEQ)          // 8192

// ---------------- scratch (__device__ globals: allocation-free) ----------------
__device__ float g_Q[MTOT * DM];             // 32 MB
__device__ float g_K[MTOT * DM];             // 32 MB
__device__ float g_V[MTOT * DM];             // 32 MB
__device__ float g_S[(long)BATCH * SEQ * SEQ]; // 64 MB (scores -> P in place)
__device__ float g_C[MTOT * DM];             // 32 MB (context)

// ---------------- GEMM tile config ----------------
#define BM 128
#define BN 128
#define BK 8
// 256 threads, each computes 8x8; accumulators kept as packed f32x2 pairs
// along the M (row) dimension so the inner product runs on fma.rn.f32x2
// (2 FMAs/instr -> full 128 FMA/cyc/SM on sm_103a).

typedef unsigned long long u64;

__device__ __forceinline__ u64 pk2(float x, float y) {
    u64 r; asm("mov.b64 %0, {%1, %2};" : "=l"(r) : "f"(x), "f"(y)); return r;
}
__device__ __forceinline__ void up2(u64 v, float& x, float& y) {
    asm("mov.b64 {%0, %1}, %2;" : "=f"(x), "=f"(y) : "l"(v));
}
__device__ __forceinline__ void fma2(u64& d, u64 a, u64 b) {
    asm("fma.rn.f32x2 %0, %1, %2, %0;" : "+l"(d) : "l"(a), "l"(b));
}

// inner 128x128x8 product: acc[i2][j] holds rows (ty*8 + 2*i2, +1), col tx*8+j
__device__ __forceinline__ void mm_tile(const float (&As)[BK][BM],
                                        const float (&Bs)[BK][BN],
                                        int tx, int ty, u64 (&acc)[4][8]) {
#pragma unroll
    for (int kk = 0; kk < BK; kk++) {
        float4 a0 = *(const float4*)&As[kk][ty * 8];
        float4 a1 = *(const float4*)&As[kk][ty * 8 + 4];
        float4 b0 = *(const float4*)&Bs[kk][tx * 8];
        float4 b1 = *(const float4*)&Bs[kk][tx * 8 + 4];
        u64 ap[4] = { pk2(a0.x, a0.y), pk2(a0.z, a0.w),
                      pk2(a1.x, a1.y), pk2(a1.z, a1.w) };
        float bf[8] = { b0.x, b0.y, b0.z, b0.w, b1.x, b1.y, b1.z, b1.w };
#pragma unroll
        for (int j = 0; j < 8; j++) {
            u64 bd = pk2(bf[j], bf[j]);
#pragma unroll
            for (int i2 = 0; i2 < 4; i2++) fma2(acc[i2][j], ap[i2], bd);
        }
    }
}

__device__ __forceinline__ void epilogue(float* Cb, u64 (&acc)[4][8],
                                         int N, int bx, int by, int tx, int ty) {
    int col = bx * BN + tx * 8;
    if (col >= N) return;                 // N is a multiple of 8 in all uses
#pragma unroll
    for (int i2 = 0; i2 < 4; i2++) {
        float r0[8], r1[8];
#pragma unroll
        for (int j = 0; j < 8; j++) up2(acc[i2][j], r0[j], r1[j]);
        long row0 = (long)by * BM + ty * 8 + 2 * i2;
        float* c0 = Cb + row0 * N + col;
        float* c1 = c0 + N;
        *(float4*)(c0)     = make_float4(r0[0], r0[1], r0[2], r0[3]);
        *(float4*)(c0 + 4) = make_float4(r0[4], r0[5], r0[6], r0[7]);
        *(float4*)(c1)     = make_float4(r1[0], r1[1], r1[2], r1[3]);
        *(float4*)(c1 + 4) = make_float4(r1[4], r1[5], r1[6], r1[7]);
    }
}

// ---- NT GEMM: C[m,n] = sum_k A[m,k] * B[n,k]  (both row-major, K-major) ----
// TRI: skip blocks strictly above the block diagonal (causal scores).
template <bool TRI>
__global__ __launch_bounds__(256, 2)
void gemm_nt(const float* __restrict__ A, const float* __restrict__ B,
             float* __restrict__ C, int M, int N, int K,
             long sA, long sB, long sC) {
    int bx = blockIdx.x, by = blockIdx.y, bz = blockIdx.z;
    if (TRI && bx > by) return;
    const float* Ab = A + (long)bz * sA;
    const float* Bb = B + (long)bz * sB;
    float* Cb = C + (long)bz * sC;

    __shared__ float As[BK][BM];
    __shared__ float Bs[BK][BN];

    int tid = threadIdx.x;
    int tx = tid & 15, ty = tid >> 4;
    int lr = tid >> 1;                 // 0..127
    int lc = (tid & 1) << 2;           // 0 or 4

    const float* Ag = Ab + ((long)by * BM + lr) * K + lc;
    const float* Bg = Bb + ((long)bx * BN + lr) * K + lc;
    bool bval = (bx * BN + lr) < N;    // M is always a multiple of BM here

    u64 acc[4][8];
#pragma unroll
    for (int i = 0; i < 4; i++)
#pragma unroll
        for (int j = 0; j < 8; j++) acc[i][j] = 0ull;

    for (int k0 = 0; k0 < K; k0 += BK) {
        float4 av = *(const float4*)(Ag + k0);
        float4 bv = bval ? *(const float4*)(Bg + k0) : make_float4(0.f, 0.f, 0.f, 0.f);
        __syncthreads();
        As[lc + 0][lr] = av.x; As[lc + 1][lr] = av.y;
        As[lc + 2][lr] = av.z; As[lc + 3][lr] = av.w;
        Bs[lc + 0][lr] = bv.x; Bs[lc + 1][lr] = bv.y;
        Bs[lc + 2][lr] = bv.z; Bs[lc + 3][lr] = bv.w;
        __syncthreads();
        mm_tile(As, Bs, tx, ty, acc);
    }
    epilogue(Cb, acc, N, bx, by, tx, ty);
}

// ---- NN GEMM with triangular k-bound: C = P @ V, P lower-triangular ----
__global__ __launch_bounds__(256, 2)
void gemm_nn_tri(const float* __restrict__ A, const float* __restrict__ B,
                 float* __restrict__ C, int M, int N, int K,
                 long sA, long sB, long sC) {
    int bx = blockIdx.x, by = blockIdx.y, bz = blockIdx.z;
    const float* Ab = A + (long)bz * sA;
    const float* Bb = B + (long)bz * sB;
    float* Cb = C + (long)bz * sC;

    __shared__ float As[BK][BM];
    __shared__ float Bs[BK][BN];

    int tid = threadIdx.x;
    int tx = tid & 15, ty = tid >> 4;
    int lr = tid >> 1, lc = (tid & 1) << 2;     // A tile (transposed store)
    int bkr = tid >> 5, bnc = (tid & 31) << 2;  // B tile (direct store)

    const float* Ag = Ab + ((long)by * BM + lr) * K + lc;
    const float* Bg = Bb + (long)bkr * N + (long)bx * BN + bnc;

    int kend = min(K, (by + 1) * BM);   // P[m,k]==0 for k>m (softmax zero-fills)

    u64 acc[4][8];
#pragma unroll
    for (int i = 0; i < 4; i++)
#pragma unroll
        for (int j = 0; j < 8; j++) acc[i][j] = 0ull;

    for (int k0 = 0; k0 < kend; k0 += BK) {
        float4 av = *(const float4*)(Ag + k0);
        float4 bv = *(const float4*)(Bg + (long)k0 * N);
        __syncthreads();
        As[lc + 0][lr] = av.x; As[lc + 1][lr] = av.y;
        As[lc + 2][lr] = av.z; As[lc + 3][lr] = av.w;
        *(float4*)&Bs[bkr][bnc] = bv;
        __syncthreads();
        mm_tile(As, Bs, tx, ty, acc);
    }
    epilogue(Cb, acc, N, bx, by, tx, ty);
}

// ---- causal softmax over row i: softmax(scale * s[0..i]), zeros for j>i ----
__global__ __launch_bounds__(256)
void softmax_causal(float* __restrict__ P, int S, float scale) {
    int row = blockIdx.x;
    int b = row / S;
    int i = row - b * S;
    float* p = P + (long)b * S * S + (long)i * S;
    int len = i + 1;
    int tid = threadIdx.x;
    __shared__ float red[8];

    float m = -3.4e38f;
    for (int j = tid; j < len; j += 256) m = fmaxf(m, p[j]);
#pragma unroll
    for (int o = 16; o > 0; o >>= 1) m = fmaxf(m, __shfl_xor_sync(0xffffffffu, m, o));
    if ((tid & 31) == 0) red[tid >> 5] = m;
    __syncthreads();
    float mb = red[0];
#pragma unroll
    for (int w = 1; w < 8; w++) mb = fmaxf(mb, red[w]);
    __syncthreads();

    float s = 0.f;
    for (int j = tid; j < len; j += 256) {
        float e = expf((p[j] - mb) * scale);
        p[j] = e;
        s += e;
    }
#pragma unroll
    for (int o = 16; o > 0; o >>= 1) s += __shfl_xor_sync(0xffffffffu, s, o);
    if ((tid & 31) == 0) red[tid >> 5] = s;
    __syncthreads();
    float sb = 0.f;
#pragma unroll
    for (int w = 0; w < 8; w++) sb += red[w];
    float inv = 1.0f / sb;

    for (int j = tid; j < len; j += 256) p[j] *= inv;
    for (int j = len + tid; j < S; j += 256) p[j] = 0.f;
}

// ---------------- launch ----------------
extern "C" void kernel_launch(void* const* d_in, const int* in_sizes, int n_in,
                              void* d_out, int out_size) {
    const float* X  = (const float*)d_in[0];
    const float* Wq = (const float*)d_in[1];
    const float* Wk = (const float*)d_in[2];
    const float* Wv = (const float*)d_in[3];
    const float* Wo = (const float*)d_in[4];
    float* out = (float*)d_out;

    static float *Q = nullptr, *Kp = nullptr, *Vp = nullptr, *Sc = nullptr, *Cx = nullptr;
    if (!Q) {
        cudaGetSymbolAddress((void**)&Q,  g_Q);
        cudaGetSymbolAddress((void**)&Kp, g_K);
        cudaGetSymbolAddress((void**)&Vp, g_V);
        cudaGetSymbolAddress((void**)&Sc, g_S);
        cudaGetSymbolAddress((void**)&Cx, g_C);
    }

    dim3 thr(256);

    // Q/K/V projections: [8192,1024] x [1024,1024]^T
    dim3 gqkv(DM / BN, MTOT / BM, 1);
    gemm_nt<false><<<gqkv, thr>>>(X, Wq, Q,  MTOT, DM, DM, 0, 0, 0);
    gemm_nt<false><<<gqkv, thr>>>(X, Wk, Kp, MTOT, DM, DM, 0, 0, 0);
    gemm_nt<false><<<gqkv, thr>>>(X, Wv, Vp, MTOT, DM, DM, 0, 0, 0);

    // scores = Q @ K^T per batch, lower-triangular blocks only
    dim3 gsc(SEQ / BN, SEQ / BM, BATCH);
    gemm_nt<true><<<gsc, thr>>>(Q, Kp, Sc, SEQ, SEQ, DM,
                                (long)SEQ * DM, (long)SEQ * DM, (long)SEQ * SEQ);

    // causal softmax in place (scale = 1/sqrt(1024))
    softmax_causal<<<BATCH * SEQ, 256>>>(Sc, SEQ, 0.03125f);

    // ctx = P @ V per batch (k-loop bounded by block diagonal)
    dim3 gav(DM / BN, SEQ / BM, BATCH);
    gemm_nn_tri<<<gav, thr>>>(Sc, Vp, Cx, SEQ, DM, SEQ,
                              (long)SEQ * SEQ, (long)SEQ * DM, (long)SEQ * DM);

    // out = ctx @ Wo^T : [8192,64]
    dim3 go((DV + BN - 1) / BN, MTOT / BM, 1);
    gemm_nt<false><<<go, thr>>>(Cx, Wo, out, MTOT, DV, DM, 0, 0, 0);
}